// round 13
// baseline (speedup 1.0000x reference)
#include <cuda_runtime.h>
#include <math.h>

#define NB 16
#define NT 500
#define NH 100
#define HOP 64
#define NS (NT*HOP)

// scratch (no allocs allowed)
static __device__ float  g_w [NB*NT*NH];     // [b][t][h] per-sample radian increment
static __device__ float  g_la[NB*NT*NH];     // [b][t][h] loudness * masked amp
static __device__ float  g_wT[NB*NH*NT];     // [b][h][t] transposed w for the scan
static __device__ float  g_G [NB*(NT+1)*NH]; // [b][t][h] frame-prefix phase G(t)
static __device__ double g_L64[NH];          // 64*log2(1..100), double
static __device__ double g_T[64];            // 2^(k/64), k=0..63, double

// ---- packed f32x2 helpers (FFMA2/FADD2 only reachable via PTX) ----
__device__ __forceinline__ unsigned long long pk2(float lo, float hi) {
    unsigned long long r; asm("mov.b64 %0, {%1,%2};" : "=l"(r) : "f"(lo), "f"(hi)); return r;
}
__device__ __forceinline__ void upk2(unsigned long long v, float& lo, float& hi) {
    asm("mov.b64 {%0,%1}, %2;" : "=f"(lo), "=f"(hi) : "l"(v));
}
__device__ __forceinline__ unsigned long long fma2(unsigned long long a,
                                                   unsigned long long b,
                                                   unsigned long long c) {
    unsigned long long d;
    asm("fma.rn.f32x2 %0, %1, %2, %3;" : "=l"(d) : "l"(a), "l"(b), "l"(c));
    return d;
}
__device__ __forceinline__ unsigned long long add2(unsigned long long a,
                                                   unsigned long long b) {
    unsigned long long d;
    asm("add.rn.f32x2 %0, %1, %2;" : "=l"(d) : "l"(a), "l"(b));
    return d;
}
__device__ __forceinline__ unsigned long long mul2(unsigned long long a,
                                                   unsigned long long b) {
    unsigned long long d;
    asm("mul.rn.f32x2 %0, %1, %2;" : "=l"(d) : "l"(a), "l"(b));
    return d;
}

// ---------------- Kernel 0: tiny tables (~0 cost) ----------------
__global__ void k_table()
{
    int h = threadIdx.x;
    if (h < NH) g_L64[h] = 64.0 * log2((double)(h + 1));
    if (h < 64) g_T[h]   = exp2((double)h * 0.015625);
}

// ---------------- Kernel 1: per-(b,t,h) prep, 8 FP64 ops via table+deg4 ----------------
__global__ void k_prep(const float* __restrict__ f0, const float* __restrict__ loud,
                       const float* __restrict__ amps, const float* __restrict__ stretch)
{
    int idx = blockIdx.x * blockDim.x + threadIdx.x;
    if (idx >= NB*NT*NH) return;
    int h  = idx % NH;
    int bt = idx / NH;

    float e = __fadd_rn(1.0f, stretch[bt]);            // 1 + harm_stretch (f32)

    // harm = h^e = 2^(e*log2 h).  y64 = 64*y;  n64 = rint(y64);  r2 = (y64-n64)/64.
    double y64 = (double)e * g_L64[h];
    int    n64 = __double2int_rn(y64);
    double d   = y64 - (double)n64;                    // exact (|d|<=0.5)
    double r2  = d * 0.015625;                         // exact (2^-6 scale)
    double z;
    z = 9.618129107628477e-3;
    z = fma(z, r2, 5.550410866482158e-2);
    z = fma(z, r2, 2.402265069591007e-1);
    z = fma(z, r2, 6.931471805599453e-1);
    z = fma(z, r2, 1.0);
    z = z * g_T[n64 & 63];
    z = __longlong_as_double(__double_as_longlong(z) + ((long long)(n64 >> 6) << 52));

    float harm = __fmul_rn((float)z, f0[bt]);          // instantaneous freq (Hz)

    const float CW = (float)(6.283185307179586476925286766559 / 44100.0);
    float w = __fmul_rn(harm, CW);                     // rad/sample
    float a = (harm > 22050.0f) ? 0.0f : amps[idx];    // nyquist mask
    float la = __fmul_rn(loud[bt], a);                 // l * a (constant within frame)

    g_w [idx] = w;
    g_la[idx] = la;
    int b = bt / NT;
    int t = bt - b * NT;
    g_wT[(b*NH + h)*NT + t] = w;
}

// ---------------- Kernel 2: per-(b,h) frame-level associative scan ----------------
__global__ void k_scan()
{
    __shared__ float tr[994];       // tree levels 0..8 packed
    int c   = blockIdx.x;           // chain = b*NH + h
    int tid = threadIdx.x;          // 64 threads

    const float* wt = g_wT + (size_t)c * NT;
    for (int t = tid; t < NT; t += 64)
        tr[t] = __fmul_rn(64.0f, wt[t]);              // exact (power-of-2 scale)
    __syncthreads();

    const int OFF[9] = {0,500,750,875,937,968,983,990,993};
    const int LEN[9] = {500,250,125, 62, 31, 15,  7,  3,  1};
#pragma unroll
    for (int L = 1; L < 9; L++) {
        int po = OFF[L-1], o = OFF[L], n = LEN[L];
        for (int k = tid; k < n; k += 64)
            tr[o + k] = __fadd_rn(tr[po + 2*k], tr[po + 2*k + 1]);
        __syncthreads();
    }

    int b = c / NH;
    int h = c - b * NH;
    size_t gbase = ((size_t)b * (NT+1)) * NH + h;
    if (tid == 0) g_G[gbase] = 0.0f;                  // G(0)

    for (int t = tid + 1; t <= NT; t += 64) {
        float G = 0.0f; bool first = true; int pos = 0;
#pragma unroll
        for (int i = 8; i >= 0; i--) {
            if ((t >> i) & 1) {
                float v = tr[OFF[i] + (pos >> i)];
                G = first ? v : __fadd_rn(G, v);
                first = false;
                pos += (1 << i);
            }
        }
        g_G[gbase + (size_t)t * NH] = G;
    }
}

// ---------------- Kernel 3: per-(b,t) frame, thread j = sample ----------------
// Hybrid sin: first POLY_ITERS iterations use packed f32x2 polynomial sine
// (FMA pipe), rest use __sinf (RRO+MUFU pipe) — balances the two pipes.
#define POLY_ITERS 6

__global__ void k_gen(float* __restrict__ out)
{
    __shared__ __align__(16) float wS[NH];
    __shared__ __align__(16) float laS[NH];
    __shared__ __align__(16) float gS[2*NH];          // G(t) and G(t+1) rows adjacent
    int bt = blockIdx.x;                              // b*NT + t
    int b  = bt / NT;
    int t  = bt - b * NT;
    int j  = threadIdx.x;                             // 0..63

    int    base  = bt * NH;
    size_t gbase = ((size_t)b * (NT+1) + t) * NH;
    {
        const float4* gw  = reinterpret_cast<const float4*>(g_w  + base);
        const float4* gla = reinterpret_cast<const float4*>(g_la + base);
        const float4* gg  = reinterpret_cast<const float4*>(g_G  + gbase);
        float4* w4  = reinterpret_cast<float4*>(wS);
        float4* la4 = reinterpret_cast<float4*>(laS);
        float4* g4  = reinterpret_cast<float4*>(gS);
        for (int k = j; k < NH/4;   k += 64) { w4[k] = gw[k]; la4[k] = gla[k]; }
        for (int k = j; k < 2*NH/4; k += 64) { g4[k] = gg[k]; }
    }
    __syncthreads();

    int jm = j + 1;
    // packed fold weights (value broadcast to both lanes); 2^i*w exact inside the FMA
    unsigned long long B5 = pk2((float)(jm & 32), (float)(jm & 32));
    unsigned long long B4 = pk2((float)(jm & 16), (float)(jm & 16));
    unsigned long long B3 = pk2((float)(jm & 8),  (float)(jm & 8));
    unsigned long long B2 = pk2((float)(jm & 4),  (float)(jm & 4));
    unsigned long long B1 = pk2((float)(jm & 2),  (float)(jm & 2));
    unsigned long long B0 = pk2((float)(jm & 1),  (float)(jm & 1));
    const float* gp = (jm == 64) ? (gS + NH) : gS;    // j=63 -> phase = G(t+1) exactly

    const float TWO_PI_F = 6.28318530717958647692f;   // fp32(2*pi) = 0x40C90FDB
    const float INV2PI   = 1.0f / 6.28318530717958647692f;
    const float MAGIC    = 12582912.0f;               // 1.5 * 2^23 round-to-int trick
    unsigned long long INV2   = pk2(INV2PI,  INV2PI);
    unsigned long long MAG2   = pk2(MAGIC,   MAGIC);
    unsigned long long NMAG2  = pk2(-MAGIC, -MAGIC);
    unsigned long long N2PI2  = pk2(-TWO_PI_F, -TWO_PI_F);
    // deg-13 odd Taylor sine coefficients (abs err <= 2.2e-5 on [-pi,pi])
    unsigned long long C6 = pk2( 1.6059044e-10f,  1.6059044e-10f);
    unsigned long long C5 = pk2(-2.5052108e-8f,  -2.5052108e-8f);
    unsigned long long C4 = pk2( 2.7557319e-6f,   2.7557319e-6f);
    unsigned long long C3 = pk2(-1.98412698e-4f, -1.98412698e-4f);
    unsigned long long C2 = pk2( 8.33333333e-3f,  8.33333333e-3f);
    unsigned long long C1 = pk2(-1.66666667e-1f, -1.66666667e-1f);
    unsigned long long C0 = pk2(1.0f, 1.0f);

    const unsigned long long* w2p = reinterpret_cast<const unsigned long long*>(wS);
    const unsigned long long* g2p = reinterpret_cast<const unsigned long long*>(gp);
    const unsigned long long* l2p = reinterpret_cast<const unsigned long long*>(laS);

    unsigned long long accA = pk2(0.f, 0.f), accB = pk2(0.f, 0.f);

#define FOLD_MOD(w2, p2, r2v)                                                    \
    p2 = fma2(B5, w2, p2); p2 = fma2(B4, w2, p2); p2 = fma2(B3, w2, p2);         \
    p2 = fma2(B2, w2, p2); p2 = fma2(B1, w2, p2); p2 = fma2(B0, w2, p2);         \
    { unsigned long long q2 = add2(fma2(p2, INV2, MAG2), NMAG2);                 \
      r2v = fma2(q2, N2PI2, p2); }

    // ---- poly-sine iterations (FMA pipe) ----
#pragma unroll
    for (int k = 0; k < POLY_ITERS; k++) {
#pragma unroll
        for (int pb = 0; pb < 2; pb++) {
            unsigned long long w2 = w2p[2*k+pb], p2 = g2p[2*k+pb], la2 = l2p[2*k+pb];
            unsigned long long r2;
            FOLD_MOD(w2, p2, r2)
            unsigned long long sq = mul2(r2, r2);
            unsigned long long u  = C6;
            u = fma2(u, sq, C5); u = fma2(u, sq, C4); u = fma2(u, sq, C3);
            u = fma2(u, sq, C2); u = fma2(u, sq, C1); u = fma2(u, sq, C0);
            unsigned long long s2 = mul2(r2, u);
            if (pb == 0) accA = fma2(la2, s2, accA);
            else         accB = fma2(la2, s2, accB);
        }
    }
    // ---- MUFU-sine iterations ----
#pragma unroll 5
    for (int k = POLY_ITERS; k < NH/4; k++) {
#pragma unroll
        for (int pb = 0; pb < 2; pb++) {
            unsigned long long w2 = w2p[2*k+pb], p2 = g2p[2*k+pb], la2 = l2p[2*k+pb];
            unsigned long long r2;
            FOLD_MOD(w2, p2, r2)
            float r0, r1; upk2(r2, r0, r1);
            unsigned long long s2 = pk2(__sinf(r0), __sinf(r1));
            if (pb == 0) accA = fma2(la2, s2, accA);
            else         accB = fma2(la2, s2, accB);
        }
    }
#undef FOLD_MOD

    float a0, a1, a2, a3;
    upk2(accA, a0, a1);
    upk2(accB, a2, a3);
    float acc = __fadd_rn(__fadd_rn(a0, a1), __fadd_rn(a2, a3));
    out[(size_t)b * NS + t * HOP + j] = acc / 100.0f;
}

extern "C" void kernel_launch(void* const* d_in, const int* in_sizes, int n_in,
                              void* d_out, int out_size)
{
    const float* f0      = (const float*)d_in[0];
    const float* loud    = (const float*)d_in[1];
    const float* amps    = (const float*)d_in[2];
    const float* stretch = (const float*)d_in[3];
    float* out = (float*)d_out;

    k_table<<<1, 128>>>();
    k_prep<<<(NB*NT*NH + 255) / 256, 256>>>(f0, loud, amps, stretch);
    k_scan<<<NB*NH, 64>>>();
    k_gen<<<NB*NT, 64>>>(out);
}

// round 17
// speedup vs baseline: 1.0282x; 1.0282x over previous
#include <cuda_runtime.h>
#include <math.h>

#define NB 16
#define NT 500
#define NH 100
#define HOP 64
#define NS (NT*HOP)

// scratch (no allocs allowed)
static __device__ float  g_w [NB*NT*NH];     // [b][t][h] per-sample radian increment
static __device__ float  g_la[NB*NT*NH];     // [b][t][h] loudness * masked amp
static __device__ float  g_G [NB*(NT+1)*NH]; // [b][t][h] frame-prefix phase G(t)
static __device__ double g_L64[NH];          // 64*log2(1..100), double
static __device__ double g_T[64];            // 2^(k/64), k=0..63, double

// ---- packed f32x2 helpers (FFMA2/FADD2 only reachable via PTX) ----
__device__ __forceinline__ unsigned long long pk2(float lo, float hi) {
    unsigned long long r; asm("mov.b64 %0, {%1,%2};" : "=l"(r) : "f"(lo), "f"(hi)); return r;
}
__device__ __forceinline__ void upk2(unsigned long long v, float& lo, float& hi) {
    asm("mov.b64 {%0,%1}, %2;" : "=f"(lo), "=f"(hi) : "l"(v));
}
__device__ __forceinline__ unsigned long long fma2(unsigned long long a,
                                                   unsigned long long b,
                                                   unsigned long long c) {
    unsigned long long d;
    asm("fma.rn.f32x2 %0, %1, %2, %3;" : "=l"(d) : "l"(a), "l"(b), "l"(c));
    return d;
}
__device__ __forceinline__ unsigned long long add2(unsigned long long a,
                                                   unsigned long long b) {
    unsigned long long d;
    asm("add.rn.f32x2 %0, %1, %2;" : "=l"(d) : "l"(a), "l"(b));
    return d;
}

// ---------------- Kernel 0: tiny tables (~0 cost) ----------------
__global__ void k_table()
{
    int h = threadIdx.x;
    if (h < NH) g_L64[h] = 64.0 * log2((double)(h + 1));
    if (h < 64) g_T[h]   = exp2((double)h * 0.015625);
}

// ---------------- Kernel 1: fused prep + frame-level scan ----------------
// One block per (b,h) chain; 64 threads loop over the 500 frames computing
// w/la (identical math to old k_prep), then run the associative-scan tree
// (identical math to old k_scan). g_wT round-trip and one launch eliminated.
__global__ void k_ps(const float* __restrict__ f0, const float* __restrict__ loud,
                     const float* __restrict__ amps, const float* __restrict__ stretch)
{
    __shared__ float tr[994];       // tree levels 0..8 packed
    int c   = blockIdx.x;           // chain = b*NH + h
    int tid = threadIdx.x;          // 64 threads
    int b   = c / NH;
    int h   = c - b * NH;

    double L64 = g_L64[h];          // broadcast load

    const float CW = (float)(6.283185307179586476925286766559 / 44100.0);

    for (int t = tid; t < NT; t += 64) {
        int bt = b * NT + t;
        float e = __fadd_rn(1.0f, stretch[bt]);        // 1 + harm_stretch (f32)

        // harm = h^e = 2^(e*log2 h): table + deg-4 Taylor, ~2^-44 rel, f32-rounded
        double y64 = (double)e * L64;
        int    n64 = __double2int_rn(y64);
        double d   = y64 - (double)n64;                // exact (|d|<=0.5)
        double r2  = d * 0.015625;                     // exact (2^-6 scale)
        double z;
        z = 9.618129107628477e-3;
        z = fma(z, r2, 5.550410866482158e-2);
        z = fma(z, r2, 2.402265069591007e-1);
        z = fma(z, r2, 6.931471805599453e-1);
        z = fma(z, r2, 1.0);
        z = z * g_T[n64 & 63];
        z = __longlong_as_double(__double_as_longlong(z) + ((long long)(n64 >> 6) << 52));

        float harm = __fmul_rn((float)z, f0[bt]);      // instantaneous freq (Hz)
        float w    = __fmul_rn(harm, CW);              // rad/sample
        float a    = (harm > 22050.0f) ? 0.0f : amps[bt*NH + h];
        float la   = __fmul_rn(loud[bt], a);

        g_w [bt*NH + h] = w;
        g_la[bt*NH + h] = la;
        tr[t] = __fmul_rn(64.0f, w);                   // exact (power-of-2 scale)
    }
    __syncthreads();

    const int OFF[9] = {0,500,750,875,937,968,983,990,993};
    const int LEN[9] = {500,250,125, 62, 31, 15,  7,  3,  1};
#pragma unroll
    for (int Lv = 1; Lv < 9; Lv++) {
        int po = OFF[Lv-1], o = OFF[Lv], n = LEN[Lv];
        for (int k = tid; k < n; k += 64)
            tr[o + k] = __fadd_rn(tr[po + 2*k], tr[po + 2*k + 1]);
        __syncthreads();
    }

    size_t gbase = ((size_t)b * (NT+1)) * NH + h;
    if (tid == 0) g_G[gbase] = 0.0f;                  // G(0)

    for (int t = tid + 1; t <= NT; t += 64) {
        float G = 0.0f; bool first = true; int pos = 0;
#pragma unroll
        for (int i = 8; i >= 0; i--) {
            if ((t >> i) & 1) {
                float v = tr[OFF[i] + (pos >> i)];
                G = first ? v : __fadd_rn(G, v);
                first = false;
                pos += (1 << i);
            }
        }
        g_G[gbase + (size_t)t * NH] = G;
    }
}

// ---------------- Kernel 2: per-(b,t) frame, thread j = sample, f32x2 packed ----------------
// (reverted to the best-measured R8 version: all-MUFU sin)
__global__ void k_gen(float* __restrict__ out)
{
    __shared__ __align__(16) float wS[NH];
    __shared__ __align__(16) float laS[NH];
    __shared__ __align__(16) float gS[2*NH];          // G(t) and G(t+1) rows adjacent
    int bt = blockIdx.x;                              // b*NT + t
    int b  = bt / NT;
    int t  = bt - b * NT;
    int j  = threadIdx.x;                             // 0..63

    int    base  = bt * NH;
    size_t gbase = ((size_t)b * (NT+1) + t) * NH;
    {
        const float4* gw  = reinterpret_cast<const float4*>(g_w  + base);
        const float4* gla = reinterpret_cast<const float4*>(g_la + base);
        const float4* gg  = reinterpret_cast<const float4*>(g_G  + gbase);
        float4* w4  = reinterpret_cast<float4*>(wS);
        float4* la4 = reinterpret_cast<float4*>(laS);
        float4* g4  = reinterpret_cast<float4*>(gS);
        for (int k = j; k < NH/4;   k += 64) { w4[k] = gw[k]; la4[k] = gla[k]; }
        for (int k = j; k < 2*NH/4; k += 64) { g4[k] = gg[k]; }
    }
    __syncthreads();

    int jm = j + 1;
    unsigned long long B5 = pk2((float)(jm & 32), (float)(jm & 32));
    unsigned long long B4 = pk2((float)(jm & 16), (float)(jm & 16));
    unsigned long long B3 = pk2((float)(jm & 8),  (float)(jm & 8));
    unsigned long long B2 = pk2((float)(jm & 4),  (float)(jm & 4));
    unsigned long long B1 = pk2((float)(jm & 2),  (float)(jm & 2));
    unsigned long long B0 = pk2((float)(jm & 1),  (float)(jm & 1));
    const float* gp = (jm == 64) ? (gS + NH) : gS;    // j=63 -> phase = G(t+1) exactly

    const float TWO_PI_F = 6.28318530717958647692f;   // fp32(2*pi) = 0x40C90FDB
    const float INV2PI   = 1.0f / 6.28318530717958647692f;
    const float MAGIC    = 12582912.0f;               // 1.5 * 2^23 round-to-int trick
    unsigned long long INV2   = pk2(INV2PI,  INV2PI);
    unsigned long long MAG2   = pk2(MAGIC,   MAGIC);
    unsigned long long NMAG2  = pk2(-MAGIC, -MAGIC);
    unsigned long long N2PI2  = pk2(-TWO_PI_F, -TWO_PI_F);

    const unsigned long long* w2p = reinterpret_cast<const unsigned long long*>(wS);
    const unsigned long long* g2p = reinterpret_cast<const unsigned long long*>(gp);
    const float2*             l2p = reinterpret_cast<const float2*>(laS);

    float a0 = 0.f, a1 = 0.f, a2 = 0.f, a3 = 0.f;
#pragma unroll 5
    for (int k = 0; k < NH/4; k++) {                  // 2 packed pairs per iter
        {
            unsigned long long w2 = w2p[2*k], p2 = g2p[2*k];
            float2 l2 = l2p[2*k];
            p2 = fma2(B5, w2, p2);                    // msb->lsb fold, bit-exact per lane
            p2 = fma2(B4, w2, p2);
            p2 = fma2(B3, w2, p2);
            p2 = fma2(B2, w2, p2);
            p2 = fma2(B1, w2, p2);
            p2 = fma2(B0, w2, p2);
            unsigned long long q2 = add2(fma2(p2, INV2, MAG2), NMAG2);  // ~round(p/2pi)
            unsigned long long r2 = fma2(q2, N2PI2, p2);                // <=1 ulp of fmodf
            float r0, r1; upk2(r2, r0, r1);
            a0 = __fmaf_rn(l2.x, __sinf(r0), a0);
            a1 = __fmaf_rn(l2.y, __sinf(r1), a1);
        }
        {
            unsigned long long w2 = w2p[2*k+1], p2 = g2p[2*k+1];
            float2 l2 = l2p[2*k+1];
            p2 = fma2(B5, w2, p2);
            p2 = fma2(B4, w2, p2);
            p2 = fma2(B3, w2, p2);
            p2 = fma2(B2, w2, p2);
            p2 = fma2(B1, w2, p2);
            p2 = fma2(B0, w2, p2);
            unsigned long long q2 = add2(fma2(p2, INV2, MAG2), NMAG2);
            unsigned long long r2 = fma2(q2, N2PI2, p2);
            float r0, r1; upk2(r2, r0, r1);
            a2 = __fmaf_rn(l2.x, __sinf(r0), a2);
            a3 = __fmaf_rn(l2.y, __sinf(r1), a3);
        }
    }
    float acc = __fadd_rn(__fadd_rn(a0, a1), __fadd_rn(a2, a3));
    out[(size_t)b * NS + t * HOP + j] = acc / 100.0f;
}

extern "C" void kernel_launch(void* const* d_in, const int* in_sizes, int n_in,
                              void* d_out, int out_size)
{
    const float* f0      = (const float*)d_in[0];
    const float* loud    = (const float*)d_in[1];
    const float* amps    = (const float*)d_in[2];
    const float* stretch = (const float*)d_in[3];
    float* out = (float*)d_out;

    k_table<<<1, 128>>>();
    k_ps<<<NB*NH, 64>>>(f0, loud, amps, stretch);
    k_gen<<<NB*NT, 64>>>(out);
}